// round 13
// baseline (speedup 1.0000x reference)
#include <cuda_runtime.h>
#include <cstdint>

// Sink + sliding-window causal attention, m16n8k16 FP16 mma.sync.
// Kernel 1: pack K,V -> fp16 MMA B-fragment images (device-global scratch).
// Kernel 2: BM=128 x BN=64 double-buffered; Q frags in smem; S chunked so the
// live register set fits 128 regs -> 2 CTAs/SM for cross-CTA latency hiding.
// Exact-zero skips: sink fast path (qt>=9) + per-warp whole-tile skips.
// B=2 H=16 N=2048 D=128.

#define Nc 2048
#define Dc 128

__device__ uint4 g_Kp[32 * 32 * 1024];    // 16 MB: (bh, kt64) -> 1024 uint4
__device__ uint4 g_Vp[32 * 32 * 1024];    // 16 MB

#define PK_SMEM 65536
// main smem: KB[2][16KB] @0 | VB[2][16KB] @32768 | Qfrag 32KB @65536
#define MAIN_SMEM 98304
#define VB_OFF 32768u
#define QF_OFF 65536u

static __device__ __forceinline__ uint32_t cvta_smem(const void* p) {
    uint32_t a;
    asm("{ .reg .u64 t; cvta.to.shared.u64 t, %1; cvt.u32.u64 %0, t; }" : "=r"(a) : "l"(p));
    return a;
}
static __device__ __forceinline__ uint32_t f16x2(float lo, float hi) {
    uint32_t d;
    asm("cvt.rn.f16x2.f32 %0, %1, %2;" : "=r"(d) : "f"(hi), "f"(lo));
    return d;
}
static __device__ __forceinline__ float ex2(float x) {
    float r; asm("ex2.approx.f32 %0, %1;" : "=f"(r) : "f"(x)); return r;
}
static __device__ __forceinline__ void mma16(float4& d, const uint4& a, uint32_t b0, uint32_t b1) {
    asm volatile("mma.sync.aligned.m16n8k16.row.col.f32.f16.f16.f32 "
                 "{%0,%1,%2,%3}, {%4,%5,%6,%7}, {%8,%9}, {%0,%1,%2,%3};"
                 : "+f"(d.x), "+f"(d.y), "+f"(d.z), "+f"(d.w)
                 : "r"(a.x), "r"(a.y), "r"(a.z), "r"(a.w), "r"(b0), "r"(b1));
}
static __device__ __forceinline__ void cp16(uint32_t s, const void* g) {
    asm volatile("cp.async.cg.shared.global [%0], [%1], 16;" :: "r"(s), "l"(g));
}
static __device__ __forceinline__ float lds_f32(uint32_t a) {
    float r; asm volatile("ld.shared.f32 %0, [%1];" : "=f"(r) : "r"(a)); return r;
}
static __device__ __forceinline__ float2 lds_f64(uint32_t a) {
    float2 r;
    asm volatile("ld.shared.v2.f32 {%0,%1}, [%2];" : "=f"(r.x), "=f"(r.y) : "r"(a));
    return r;
}
static __device__ __forceinline__ uint4 lds_u128(uint32_t a) {
    uint4 r;
    asm volatile("ld.shared.v4.u32 {%0,%1,%2,%3}, [%4];"
                 : "=r"(r.x), "=r"(r.y), "=r"(r.z), "=r"(r.w) : "r"(a));
    return r;
}
static __device__ __forceinline__ void sts_u128(uint32_t a, uint32_t x, uint32_t y,
                                                uint32_t z, uint32_t w) {
    asm volatile("st.shared.v4.u32 [%0], {%1,%2,%3,%4};"
                 :: "r"(a), "r"(x), "r"(y), "r"(z), "r"(w));
}
static __device__ __forceinline__ bool validj(int i, int j, int ns, int win) {
    return (j <= i) && ((j < ns) || ((i - j) < win));
}
#define CP_COMMIT() asm volatile("cp.async.commit_group;" ::: "memory")
#define CP_WAIT0()  asm volatile("cp.async.wait_group 0;" ::: "memory")

static __device__ __forceinline__ void issue_raw(const float* g, uint32_t dst, int tid) {
    #pragma unroll
    for (int i2 = 0; i2 < 8; i2++) {
        int task = tid + i2 * 256;
        int key = task >> 5, gg = task & 31;
        uint32_t off = (uint32_t)(key * 512 + ((gg ^ (key & 7)) << 4));
        cp16(dst + off, g + key * 128 + gg * 4);
    }
}

// ====================== pack kernel (layout unchanged since R10) =============
__global__ __launch_bounds__(256, 1)
void pack_kernel(const float* __restrict__ K, const float* __restrict__ V)
{
    extern __shared__ char smc[];
    const uint32_t KrawB = cvta_smem(smc);
    const uint32_t VrawB = KrawB + 32768u;

    const int bh = blockIdx.y;
    const int kt = blockIdx.x;            // 0..31 (64-key tiles)
    const int tid  = threadIdx.x;
    const int lane = tid & 31;
    const int wid  = tid >> 5;
    const int lq   = lane >> 2;
    const int lr   = lane & 3;

    issue_raw(K + ((size_t)bh * Nc + (size_t)kt * 64) * Dc, KrawB, tid);
    issue_raw(V + ((size_t)bh * Nc + (size_t)kt * 64) * Dc, VrawB, tid);
    CP_COMMIT();
    CP_WAIT0();
    __syncthreads();

    uint4* Kp = g_Kp + ((size_t)(bh * 32 + kt) << 10);
    uint4* Vp = g_Vp + ((size_t)(bh * 32 + kt) << 10);

    #pragma unroll
    for (int i2 = 0; i2 < 4; i2++) {
        int combo = wid + 8 * i2;
        int s = combo >> 2, gp = combo & 3;
        int kA = 16 * gp + lq;
        uint32_t gL = (uint32_t)((4 * s + (lr >> 1)) ^ lq);
        uint32_t gH = (uint32_t)((4 * s + 2 + (lr >> 1)) ^ lq);
        uint32_t ofs = (uint32_t)((lr & 1) * 8);
        uint32_t rowA = KrawB + (uint32_t)(kA * 512);
        float2 fAlo = lds_f64(rowA + (gL << 4) + ofs);
        float2 fAhi = lds_f64(rowA + (gH << 4) + ofs);
        float2 fBlo = lds_f64(rowA + 4096u + (gL << 4) + ofs);
        float2 fBhi = lds_f64(rowA + 4096u + (gH << 4) + ofs);
        Kp[combo * 32 + lane] = make_uint4(
            f16x2(fAlo.x, fAlo.y), f16x2(fAhi.x, fAhi.y),
            f16x2(fBlo.x, fBlo.y), f16x2(fBhi.x, fBhi.y));
    }

    #pragma unroll
    for (int i2 = 0; i2 < 4; i2++) {
        int combo = wid + 8 * i2;
        int t = combo >> 3, m = combo & 7;
        int k0 = 16 * t + 2 * lr;
        uint32_t gA = (uint32_t)(4 * m + (lq >> 2));
        uint32_t oA = (uint32_t)((lq & 3) * 4);
        uint32_t r0 = VrawB + (uint32_t)(k0 * 512);
        uint32_t r1 = r0 + 512u;
        uint32_t xe = (uint32_t)(2 * lr);
        uint32_t xo = xe + 1u;
        float v00 = lds_f32(r0 + (((gA)      ^ xe) << 4) + oA);
        float v10 = lds_f32(r1 + (((gA)      ^ xo) << 4) + oA);
        float v20 = lds_f32(r0 + 4096u + (((gA) ^ xe) << 4) + oA);
        float v30 = lds_f32(r1 + 4096u + (((gA) ^ xo) << 4) + oA);
        float v01 = lds_f32(r0 + (((gA + 2u) ^ xe) << 4) + oA);
        float v11 = lds_f32(r1 + (((gA + 2u) ^ xo) << 4) + oA);
        float v21 = lds_f32(r0 + 4096u + (((gA + 2u) ^ xe) << 4) + oA);
        float v31 = lds_f32(r1 + 4096u + (((gA + 2u) ^ xo) << 4) + oA);
        Vp[combo * 32 + lane] = make_uint4(
            f16x2(v00, v10), f16x2(v20, v30),
            f16x2(v01, v11), f16x2(v31 * 0.0f + v21, v31));   // == (v21, v31)
    }
}

// ====================== main kernel ==========================================
// stream one packed 16KB (64-key) tile: 1024 uint4 / 256 thr = 4 cp16 each
static __device__ __forceinline__ void issue_packed(const uint4* g, uint32_t dst, int tid) {
    #pragma unroll
    for (int i2 = 0; i2 < 4; i2++) {
        int idx = tid + i2 * 256;
        cp16(dst + (uint32_t)(idx << 4), g + idx);
    }
}

__global__ __launch_bounds__(256, 2)
void sink_attn_v13_kernel(const float* __restrict__ Q, float* __restrict__ O,
                          const int* __restrict__ p_sink, const int* __restrict__ p_win)
{
    extern __shared__ char smc[];
    const uint32_t smb = cvta_smem(smc);
    const uint32_t KBB = smb;
    const uint32_t VBB = smb + VB_OFF;

    const int ns  = *p_sink;
    const int win = *p_win;

    const int bh = blockIdx.y;
    const int qt = 15 - (int)blockIdx.x;     // heavy CTAs first
    const int m0 = qt << 7;

    const int tid  = threadIdx.x;
    const int lane = tid & 31;
    const int wid  = tid >> 5;               // 0..7: rows wid*16..+15
    const int lq   = lane >> 2;
    const int lr   = lane & 3;

    const int iw0 = m0 + wid * 16;
    const int i0  = iw0 + lq;
    const int i1  = i0 + 8;

    const uint4* Kp0 = g_Kp + ((size_t)bh << 15);
    const uint4* Vp0 = g_Vp + ((size_t)bh << 15);

    // ---- prologue: issue 64-key tile 0 (stage 0) ----
    issue_packed(Kp0, KBB, tid);
    issue_packed(Vp0, VBB, tid);
    CP_COMMIT();

    // ---- Q -> fp16 A-frags, stored to smem (each warp its own 4KB region) ----
    const uint32_t Qw = smb + QF_OFF + (uint32_t)(wid * 4096 + lane * 16);
    {
        const float qsc = 1.4426950408889634f * 0.08838834764831845f;
        const float2* Q0 = (const float2*)(Q + ((size_t)bh * Nc + i0) * Dc);
        const float2* Q1 = (const float2*)(Q + ((size_t)bh * Nc + i1) * Dc);
        #pragma unroll
        for (int s = 0; s < 8; s++) {
            int e = 8 * s + lr;
            float2 a = __ldg(Q0 + e), b = __ldg(Q1 + e);
            float2 c = __ldg(Q0 + e + 4), d = __ldg(Q1 + e + 4);
            sts_u128(Qw + (uint32_t)(s * 512),
                     f16x2(a.x * qsc, a.y * qsc), f16x2(b.x * qsc, b.y * qsc),
                     f16x2(c.x * qsc, c.y * qsc), f16x2(d.x * qsc, d.y * qsc));
        }
    }

    float4 o[16];
    #pragma unroll
    for (int nf = 0; nf < 16; nf++) o[nf] = make_float4(0.f, 0.f, 0.f, 0.f);
    float l0 = 0.f, l1 = 0.f;

    const int kt_hi = 2 * qt + 1;            // 64-key tiles
    int kt1;
    { int lo = m0 - win + 1; kt1 = (lo < 64) ? 1 : (lo >> 6); }

    int kt = 0, stage = 0;
    while (true) {
        CP_WAIT0();
        __syncthreads();   // stage's KB/VB visible; prev stage fully consumed

        const int ktn = (kt == 0) ? kt1 : kt + 1;
        if (kt != kt_hi) {
            issue_packed(Kp0 + ((size_t)ktn << 10), KBB + (uint32_t)((stage ^ 1) * 16384), tid);
            issue_packed(Vp0 + ((size_t)ktn << 10), VBB + (uint32_t)((stage ^ 1) * 16384), tid);
            CP_COMMIT();
        }

        const uint32_t KBt = KBB + (uint32_t)(stage * 16384) + (uint32_t)(lane << 4);
        const uint32_t VBt = VBB + (uint32_t)(stage * 16384) + (uint32_t)(lane << 4);
        const int ktb = kt << 6;

        // sink-only fast path: keys 16..63 of tile 0 invalid for every row
        const bool sinkFast = (kt == 0) && (m0 - 63 >= win) && (ns <= 16);
        if (sinkFast) {
            float4 s0 = make_float4(0.f, 0.f, 0.f, 0.f);
            float4 s1 = make_float4(0.f, 0.f, 0.f, 0.f);
            #pragma unroll
            for (int s = 0; s < 8; s++) {
                uint4 A = lds_u128(Qw + (uint32_t)(s * 512));
                uint4 b = lds_u128(KBt + (uint32_t)(s << 11));
                mma16(s0, A, b.x, b.y);
                mma16(s1, A, b.z, b.w);
            }
            uint4 pa0;
            {
                float p[2][4];
                #pragma unroll
                for (int h = 0; h < 2; h++) {
                    float4 s4 = (h == 0) ? s0 : s1;
                    float p0 = ex2(s4.x), p1 = ex2(s4.y), p2 = ex2(s4.z), p3 = ex2(s4.w);
                    int j0 = h * 8 + 2 * lr, j1 = j0 + 1;
                    if (!validj(i0, j0, ns, win)) p0 = 0.f;
                    if (!validj(i0, j1, ns, win)) p1 = 0.f;
                    if (!validj(i1, j0, ns, win)) p2 = 0.f;
                    if (!validj(i1, j1, ns, win)) p3 = 0.f;
                    l0 += p0 + p1;
                    l1 += p2 + p3;
                    p[h][0] = p0; p[h][1] = p1; p[h][2] = p2; p[h][3] = p3;
                }
                pa0.x = f16x2(p[0][0], p[0][1]);
                pa0.y = f16x2(p[0][2], p[0][3]);
                pa0.z = f16x2(p[1][0], p[1][1]);
                pa0.w = f16x2(p[1][2], p[1][3]);
            }
            #pragma unroll
            for (int m = 0; m < 8; m++) {
                uint4 vb = lds_u128(VBt + (uint32_t)(m << 9));
                mma16(o[2 * m],     pa0, vb.x, vb.y);
                mma16(o[2 * m + 1], pa0, vb.z, vb.w);
            }
        } else {
            // per-warp whole-tile exact-zero skip (warp-uniform branch)
            const bool skipW = (ktb > iw0 + 15) ||
                               ((iw0 - ktb - 63 >= win) && (ktb >= ns));
            if (!skipW) {
                const bool fullw = (ktb + 63 <= iw0) && (iw0 + 15 - ktb < win);
                uint4 pa[4];
                // S + softmax in two 2-gp chunks (keeps live regs small)
                #pragma unroll
                for (int gpp = 0; gpp < 2; gpp++) {
                    float4 sf[4];
                    #pragma unroll
                    for (int g = 0; g < 4; g++) sf[g] = make_float4(0.f, 0.f, 0.f, 0.f);
                    #pragma unroll
                    for (int s = 0; s < 8; s++) {
                        uint4 A = lds_u128(Qw + (uint32_t)(s * 512));
                        uint32_t rb = KBt + (uint32_t)(s << 11) + (uint32_t)(gpp << 10);
                        uint4 b0 = lds_u128(rb);
                        mma16(sf[0], A, b0.x, b0.y);
                        mma16(sf[1], A, b0.z, b0.w);
                        uint4 b1 = lds_u128(rb + 512u);
                        mma16(sf[2], A, b1.x, b1.y);
                        mma16(sf[3], A, b1.z, b1.w);
                    }
                    // softmax for groups g = 4*gpp .. 4*gpp+3
                    #pragma unroll
                    for (int tt = 0; tt < 2; tt++) {
                        float p[2][4];
                        #pragma unroll
                        for (int h = 0; h < 2; h++) {
                            const int g = 4 * gpp + 2 * tt + h;
                            float4 s4 = sf[2 * tt + h];
                            float p0 = ex2(s4.x), p1 = ex2(s4.y), p2 = ex2(s4.z), p3 = ex2(s4.w);
                            if (!fullw) {
                                int j0 = ktb + g * 8 + 2 * lr, j1 = j0 + 1;
                                if (!validj(i0, j0, ns, win)) p0 = 0.f;
                                if (!validj(i0, j1, ns, win)) p1 = 0.f;
                                if (!validj(i1, j0, ns, win)) p2 = 0.f;
                                if (!validj(i1, j1, ns, win)) p3 = 0.f;
                            }
                            l0 += p0 + p1;
                            l1 += p2 + p3;
                            p[h][0] = p0; p[h][1] = p1; p[h][2] = p2; p[h][3] = p3;
                        }
                        pa[2 * gpp + tt].x = f16x2(p[0][0], p[0][1]);
                        pa[2 * gpp + tt].y = f16x2(p[0][2], p[0][3]);
                        pa[2 * gpp + tt].z = f16x2(p[1][0], p[1][1]);
                        pa[2 * gpp + tt].w = f16x2(p[1][2], p[1][3]);
                    }
                }
                // PV: 4 ksteps x 8 dim-pairs
                #pragma unroll
                for (int t = 0; t < 4; t++) {
                    uint32_t rb = VBt + (uint32_t)(t << 12);
                    const uint4 A = pa[t];
                    #pragma unroll
                    for (int m = 0; m < 8; m++) {
                        uint4 vb = lds_u128(rb + (uint32_t)(m << 9));
                        mma16(o[2 * m],     A, vb.x, vb.y);
                        mma16(o[2 * m + 1], A, vb.z, vb.w);
                    }
                }
            }
        }

        if (kt == kt_hi) break;
        kt = ktn; stage ^= 1;
    }

    // ---- epilogue: reduce l over 4 lanes sharing lq, normalize, store ----
    l0 += __shfl_xor_sync(0xffffffffu, l0, 1);
    l0 += __shfl_xor_sync(0xffffffffu, l0, 2);
    l1 += __shfl_xor_sync(0xffffffffu, l1, 1);
    l1 += __shfl_xor_sync(0xffffffffu, l1, 2);
    const float inv0 = 1.0f / l0;
    const float inv1 = 1.0f / l1;

    float* O0 = O + ((size_t)bh * Nc + i0) * Dc;
    float* O1 = O + ((size_t)bh * Nc + i1) * Dc;
    #pragma unroll
    for (int nf = 0; nf < 16; nf++) {
        int d = nf * 8 + 2 * lr;
        *(float2*)(O0 + d) = make_float2(o[nf].x * inv0, o[nf].y * inv0);
        *(float2*)(O1 + d) = make_float2(o[nf].z * inv1, o[nf].w * inv1);
    }
}

extern "C" void kernel_launch(void* const* d_in, const int* in_sizes, int n_in,
                              void* d_out, int out_size)
{
    const float* q = (const float*)d_in[0];
    const float* k = (const float*)d_in[1];
    const float* v = (const float*)d_in[2];
    const int* num_sink  = (const int*)d_in[3];
    const int* window_sz = (const int*)d_in[4];
    float* out = (float*)d_out;

    cudaFuncSetAttribute(pack_kernel,
                         cudaFuncAttributeMaxDynamicSharedMemorySize, PK_SMEM);
    cudaFuncSetAttribute(sink_attn_v13_kernel,
                         cudaFuncAttributeMaxDynamicSharedMemorySize, MAIN_SMEM);

    pack_kernel<<<dim3(32, 32), 256, PK_SMEM>>>(k, v);
    sink_attn_v13_kernel<<<dim3(16, 32), 256, MAIN_SMEM>>>(q, out, num_sink, window_sz);
}

// round 14
// speedup vs baseline: 1.1891x; 1.1891x over previous
#include <cuda_runtime.h>
#include <cuda_fp16.h>
#include <cstdint>

// Sink + sliding-window causal attention, m16n8k16 FP16 mma.sync.
// Kernel 1: pack K,V -> fp16 MMA B-fragment images (device scratch), occ 3.
// Kernel 2: BM=128 x BN=128 via cp.async double-buffer; softmax with
// ex2.approx.f16x2 (half the MUFU ops); exact-zero skips (sink fast path,
// per-warp half skips). B=2 H=16 N=2048 D=128.

#define Nc 2048
#define Dc 128

__device__ uint4 g_Kp[32 * 32 * 1024];    // 16 MB: (bh, kt64) -> 1024 uint4
__device__ uint4 g_Vp[32 * 32 * 1024];    // 16 MB

#define PK_SMEM 65536
#define MAIN_SMEM 131072
#define VB_OFF 65536u

static __device__ __forceinline__ uint32_t cvta_smem(const void* p) {
    uint32_t a;
    asm("{ .reg .u64 t; cvta.to.shared.u64 t, %1; cvt.u32.u64 %0, t; }" : "=r"(a) : "l"(p));
    return a;
}
static __device__ __forceinline__ uint32_t f16x2(float lo, float hi) {
    uint32_t d;   // first source -> upper half
    asm("cvt.rn.f16x2.f32 %0, %1, %2;" : "=r"(d) : "f"(hi), "f"(lo));
    return d;
}
static __device__ __forceinline__ uint32_t h2exp2(uint32_t s2) {
    uint32_t r; asm("ex2.approx.f16x2 %0, %1;" : "=r"(r) : "r"(s2)); return r;
}
static __device__ __forceinline__ void mma16(float4& d, const uint4& a, uint32_t b0, uint32_t b1) {
    asm volatile("mma.sync.aligned.m16n8k16.row.col.f32.f16.f16.f32 "
                 "{%0,%1,%2,%3}, {%4,%5,%6,%7}, {%8,%9}, {%0,%1,%2,%3};"
                 : "+f"(d.x), "+f"(d.y), "+f"(d.z), "+f"(d.w)
                 : "r"(a.x), "r"(a.y), "r"(a.z), "r"(a.w), "r"(b0), "r"(b1));
}
static __device__ __forceinline__ void cp16(uint32_t s, const void* g) {
    asm volatile("cp.async.cg.shared.global [%0], [%1], 16;" :: "r"(s), "l"(g));
}
static __device__ __forceinline__ float lds_f32(uint32_t a) {
    float r; asm volatile("ld.shared.f32 %0, [%1];" : "=f"(r) : "r"(a)); return r;
}
static __device__ __forceinline__ float2 lds_f64(uint32_t a) {
    float2 r;
    asm volatile("ld.shared.v2.f32 {%0,%1}, [%2];" : "=f"(r.x), "=f"(r.y) : "r"(a));
    return r;
}
static __device__ __forceinline__ uint4 lds_u128(uint32_t a) {
    uint4 r;
    asm volatile("ld.shared.v4.u32 {%0,%1,%2,%3}, [%4];"
                 : "=r"(r.x), "=r"(r.y), "=r"(r.z), "=r"(r.w) : "r"(a));
    return r;
}
static __device__ __forceinline__ bool validj(int i, int j, int ns, int win) {
    return (j <= i) && ((j < ns) || ((i - j) < win));
}
static __device__ __forceinline__ void lacc(uint32_t p2, float& l) {
    __half2 h = *reinterpret_cast<__half2*>(&p2);
    float2 f = __half22float2(h);
    l += f.x + f.y;
}
#define CP_COMMIT() asm volatile("cp.async.commit_group;" ::: "memory")
#define CP_WAIT0()  asm volatile("cp.async.wait_group 0;" ::: "memory")

static __device__ __forceinline__ void issue_raw(const float* g, uint32_t dst, int tid) {
    #pragma unroll
    for (int i2 = 0; i2 < 8; i2++) {
        int task = tid + i2 * 256;
        int key = task >> 5, gg = task & 31;
        uint32_t off = (uint32_t)(key * 512 + ((gg ^ (key & 7)) << 4));
        cp16(dst + off, g + key * 128 + gg * 4);
    }
}

// ====================== pack kernel (layout unchanged since R10; occ 3) ======
__global__ __launch_bounds__(256, 3)
void pack_kernel(const float* __restrict__ K, const float* __restrict__ V)
{
    extern __shared__ char smc[];
    const uint32_t KrawB = cvta_smem(smc);
    const uint32_t VrawB = KrawB + 32768u;

    const int bh = blockIdx.y;
    const int kt = blockIdx.x;            // 0..31 (64-key tiles)
    const int tid  = threadIdx.x;
    const int lane = tid & 31;
    const int wid  = tid >> 5;
    const int lq   = lane >> 2;
    const int lr   = lane & 3;

    issue_raw(K + ((size_t)bh * Nc + (size_t)kt * 64) * Dc, KrawB, tid);
    issue_raw(V + ((size_t)bh * Nc + (size_t)kt * 64) * Dc, VrawB, tid);
    CP_COMMIT();
    CP_WAIT0();
    __syncthreads();

    uint4* Kp = g_Kp + ((size_t)(bh * 32 + kt) << 10);
    uint4* Vp = g_Vp + ((size_t)(bh * 32 + kt) << 10);

    #pragma unroll
    for (int i2 = 0; i2 < 4; i2++) {
        int combo = wid + 8 * i2;
        int s = combo >> 2, gp = combo & 3;
        int kA = 16 * gp + lq;
        uint32_t gL = (uint32_t)((4 * s + (lr >> 1)) ^ lq);
        uint32_t gH = (uint32_t)((4 * s + 2 + (lr >> 1)) ^ lq);
        uint32_t ofs = (uint32_t)((lr & 1) * 8);
        uint32_t rowA = KrawB + (uint32_t)(kA * 512);
        float2 fAlo = lds_f64(rowA + (gL << 4) + ofs);
        float2 fAhi = lds_f64(rowA + (gH << 4) + ofs);
        float2 fBlo = lds_f64(rowA + 4096u + (gL << 4) + ofs);
        float2 fBhi = lds_f64(rowA + 4096u + (gH << 4) + ofs);
        Kp[combo * 32 + lane] = make_uint4(
            f16x2(fAlo.x, fAlo.y), f16x2(fAhi.x, fAhi.y),
            f16x2(fBlo.x, fBlo.y), f16x2(fBhi.x, fBhi.y));
    }

    #pragma unroll
    for (int i2 = 0; i2 < 4; i2++) {
        int combo = wid + 8 * i2;
        int t = combo >> 3, m = combo & 7;
        int k0 = 16 * t + 2 * lr;
        uint32_t gA = (uint32_t)(4 * m + (lq >> 2));
        uint32_t oA = (uint32_t)((lq & 3) * 4);
        uint32_t r0 = VrawB + (uint32_t)(k0 * 512);
        uint32_t r1 = r0 + 512u;
        uint32_t xe = (uint32_t)(2 * lr);
        uint32_t xo = xe + 1u;
        float v00 = lds_f32(r0 + (((gA)      ^ xe) << 4) + oA);
        float v10 = lds_f32(r1 + (((gA)      ^ xo) << 4) + oA);
        float v20 = lds_f32(r0 + 4096u + (((gA) ^ xe) << 4) + oA);
        float v30 = lds_f32(r1 + 4096u + (((gA) ^ xo) << 4) + oA);
        float v01 = lds_f32(r0 + (((gA + 2u) ^ xe) << 4) + oA);
        float v11 = lds_f32(r1 + (((gA + 2u) ^ xo) << 4) + oA);
        float v21 = lds_f32(r0 + 4096u + (((gA + 2u) ^ xe) << 4) + oA);
        float v31 = lds_f32(r1 + 4096u + (((gA + 2u) ^ xo) << 4) + oA);
        Vp[combo * 32 + lane] = make_uint4(
            f16x2(v00, v10), f16x2(v20, v30),
            f16x2(v01, v11), f16x2(v21, v31));
    }
}

// ====================== main kernel ==========================================
static __device__ __forceinline__ void issue_packed2(const uint4* g, uint32_t dst, int tid) {
    #pragma unroll
    for (int i2 = 0; i2 < 8; i2++) {
        int idx = tid + i2 * 256;
        cp16(dst + (uint32_t)(idx << 4), g + idx);
    }
}

static __device__ __forceinline__ void s_half(float4* sf, const uint4* qa, uint32_t KBt) {
    #pragma unroll
    for (int g = 0; g < 8; g++) sf[g] = make_float4(0.f, 0.f, 0.f, 0.f);
    #pragma unroll
    for (int s = 0; s < 8; s++) {
        uint32_t rb = KBt + (uint32_t)(s << 11);
        const uint4 A = qa[s];
        #pragma unroll
        for (int gp = 0; gp < 4; gp++) {
            uint4 b = lds_u128(rb + (uint32_t)(gp << 9));
            mma16(sf[2 * gp],     A, b.x, b.y);
            mma16(sf[2 * gp + 1], A, b.z, b.w);
        }
    }
}
// softmax with packed fp16 exp2: s pairs -> f16x2 -> ex2.approx.f16x2 -> bit mask
static __device__ __forceinline__ void softmax_half(const float4* sf, uint4* pa,
                                                    int ktb, int iw0, int i0, int i1,
                                                    int lr, int ns, int win,
                                                    float& l0, float& l1) {
    const bool fullw = (ktb + 63 <= iw0) && (iw0 + 15 - ktb < win);
    #pragma unroll
    for (int t = 0; t < 4; t++) {
        uint32_t q[2][2];   // [h][row-half]: packed p pairs
        #pragma unroll
        for (int h = 0; h < 2; h++) {
            const int g = 2 * t + h;
            float4 s4 = sf[g];
            uint32_t p0 = h2exp2(f16x2(s4.x, s4.y));   // row i0: keys j0,j1
            uint32_t p1 = h2exp2(f16x2(s4.z, s4.w));   // row i1: keys j0,j1
            if (!fullw) {
                int j0 = ktb + g * 8 + 2 * lr, j1 = j0 + 1;
                uint32_t m0 = (validj(i0, j0, ns, win) ? 0x0000FFFFu : 0u)
                            | (validj(i0, j1, ns, win) ? 0xFFFF0000u : 0u);
                uint32_t m1 = (validj(i1, j0, ns, win) ? 0x0000FFFFu : 0u)
                            | (validj(i1, j1, ns, win) ? 0xFFFF0000u : 0u);
                p0 &= m0;
                p1 &= m1;
            }
            lacc(p0, l0);
            lacc(p1, l1);
            q[h][0] = p0; q[h][1] = p1;
        }
        pa[t].x = q[0][0];
        pa[t].y = q[0][1];
        pa[t].z = q[1][0];
        pa[t].w = q[1][1];
    }
}
static __device__ __forceinline__ void pv_half(float4* o, const uint4* pa, uint32_t VBt) {
    #pragma unroll
    for (int t = 0; t < 4; t++) {
        uint32_t rb = VBt + (uint32_t)(t << 12);
        const uint4 A = pa[t];
        #pragma unroll
        for (int m = 0; m < 8; m++) {
            uint4 vb = lds_u128(rb + (uint32_t)(m << 9));
            mma16(o[2 * m],     A, vb.x, vb.y);
            mma16(o[2 * m + 1], A, vb.z, vb.w);
        }
    }
}

__global__ __launch_bounds__(256, 1)
void sink_attn_v14_kernel(const float* __restrict__ Q, float* __restrict__ O,
                          const int* __restrict__ p_sink, const int* __restrict__ p_win)
{
    extern __shared__ char smc[];
    const uint32_t KBB = cvta_smem(smc);
    const uint32_t VBB = KBB + VB_OFF;

    const int ns  = *p_sink;
    const int win = *p_win;

    const int bh = blockIdx.y;
    const int qt = 15 - (int)blockIdx.x;     // heavy CTAs first
    const int m0 = qt << 7;

    const int tid  = threadIdx.x;
    const int lane = tid & 31;
    const int wid  = tid >> 5;               // 0..7: rows wid*16..+15
    const int lq   = lane >> 2;
    const int lr   = lane & 3;

    const int iw0 = m0 + wid * 16;
    const int i0  = iw0 + lq;
    const int i1  = i0 + 8;

    const uint4* Kp0 = g_Kp + ((size_t)bh << 15);
    const uint4* Vp0 = g_Vp + ((size_t)bh << 15);

    // ---- prologue: issue 128-key tile 0 (stage 0) ----
    issue_packed2(Kp0, KBB, tid);
    issue_packed2(Vp0, VBB, tid);
    CP_COMMIT();

    // ---- Q -> fp16 A-frags (scale*log2e folded) ----
    const float qsc = 1.4426950408889634f * 0.08838834764831845f;
    uint4 qa[8];
    {
        const float2* Q0 = (const float2*)(Q + ((size_t)bh * Nc + i0) * Dc);
        const float2* Q1 = (const float2*)(Q + ((size_t)bh * Nc + i1) * Dc);
        #pragma unroll
        for (int s = 0; s < 8; s++) {
            int e = 8 * s + lr;
            float2 a = __ldg(Q0 + e), b = __ldg(Q1 + e);
            float2 c = __ldg(Q0 + e + 4), d = __ldg(Q1 + e + 4);
            qa[s].x = f16x2(a.x * qsc, a.y * qsc);
            qa[s].y = f16x2(b.x * qsc, b.y * qsc);
            qa[s].z = f16x2(c.x * qsc, c.y * qsc);
            qa[s].w = f16x2(d.x * qsc, d.y * qsc);
        }
    }

    float4 o[16];
    #pragma unroll
    for (int nf = 0; nf < 16; nf++) o[nf] = make_float4(0.f, 0.f, 0.f, 0.f);
    float l0 = 0.f, l1 = 0.f;

    const int kt_hi = qt;                    // 128-key tile units
    int kt1;
    { int lo = m0 - win + 1; kt1 = (lo < 128) ? 1 : (lo >> 7); }

    int kt = 0, stage = 0;
    while (true) {
        CP_WAIT0();
        __syncthreads();   // stage's KB/VB visible; prev stage fully consumed

        const int ktn = (kt == 0) ? kt1 : kt + 1;
        if (kt != kt_hi) {
            issue_packed2(Kp0 + ((size_t)(2 * ktn) << 10),
                          KBB + (uint32_t)((stage ^ 1) * 32768), tid);
            issue_packed2(Vp0 + ((size_t)(2 * ktn) << 10),
                          VBB + (uint32_t)((stage ^ 1) * 32768), tid);
            CP_COMMIT();
        }

        const uint32_t KBt = KBB + (uint32_t)(stage * 32768) + (uint32_t)(lane << 4);
        const uint32_t VBt = VBB + (uint32_t)(stage * 32768) + (uint32_t)(lane << 4);
        const int ktb = kt << 7;

        // sink-only fast path: window part of tile 0 invalid for every row
        const bool sinkFast = (kt == 0) && (m0 - 127 >= win) && (ns <= 16);
        if (sinkFast) {
            float4 s0 = make_float4(0.f, 0.f, 0.f, 0.f);
            float4 s1 = make_float4(0.f, 0.f, 0.f, 0.f);
            #pragma unroll
            for (int s = 0; s < 8; s++) {
                uint4 b = lds_u128(KBt + (uint32_t)(s << 11));
                mma16(s0, qa[s], b.x, b.y);
                mma16(s1, qa[s], b.z, b.w);
            }
            uint4 pa0;
            {
                uint32_t q[2][2];
                #pragma unroll
                for (int h = 0; h < 2; h++) {
                    float4 s4 = (h == 0) ? s0 : s1;
                    uint32_t p0 = h2exp2(f16x2(s4.x, s4.y));
                    uint32_t p1 = h2exp2(f16x2(s4.z, s4.w));
                    int j0 = h * 8 + 2 * lr, j1 = j0 + 1;
                    uint32_t m0m = (validj(i0, j0, ns, win) ? 0x0000FFFFu : 0u)
                                 | (validj(i0, j1, ns, win) ? 0xFFFF0000u : 0u);
                    uint32_t m1m = (validj(i1, j0, ns, win) ? 0x0000FFFFu : 0u)
                                 | (validj(i1, j1, ns, win) ? 0xFFFF0000u : 0u);
                    p0 &= m0m;
                    p1 &= m1m;
                    lacc(p0, l0);
                    lacc(p1, l1);
                    q[h][0] = p0; q[h][1] = p1;
                }
                pa0.x = q[0][0]; pa0.y = q[0][1];
                pa0.z = q[1][0]; pa0.w = q[1][1];
            }
            #pragma unroll
            for (int m = 0; m < 8; m++) {
                uint4 vb = lds_u128(VBt + (uint32_t)(m << 9));
                mma16(o[2 * m],     pa0, vb.x, vb.y);
                mma16(o[2 * m + 1], pa0, vb.z, vb.w);
            }
        } else {
            // per-warp exact-zero half skips (warp-uniform branches)
            const bool skipA = (iw0 - ktb - 63 >= win) && (ktb >= ns);  // window edge
            const bool skipB = (ktb + 64 > iw0 + 15);                    // diagonal

            float4 sfA[8];
            uint4 paA[4];
            if (!skipA) s_half(sfA, qa, KBt);
            float4 sfB[8];
            if (!skipA) softmax_half(sfA, paA, ktb, iw0, i0, i1, lr, ns, win, l0, l1);
            if (!skipB) s_half(sfB, qa, KBt + 16384u);
            uint4 paB[4];
            if (!skipA) pv_half(o, paA, VBt);
            if (!skipB) softmax_half(sfB, paB, ktb + 64, iw0, i0, i1, lr, ns, win, l0, l1);
            if (!skipB) pv_half(o, paB, VBt + 16384u);
        }

        if (kt == kt_hi) break;
        kt = ktn; stage ^= 1;
    }

    // ---- epilogue: reduce l over 4 lanes sharing lq, normalize, store ----
    l0 += __shfl_xor_sync(0xffffffffu, l0, 1);
    l0 += __shfl_xor_sync(0xffffffffu, l0, 2);
    l1 += __shfl_xor_sync(0xffffffffu, l1, 1);
    l1 += __shfl_xor_sync(0xffffffffu, l1, 2);
    const float inv0 = 1.0f / l0;
    const float inv1 = 1.0f / l1;

    float* O0 = O + ((size_t)bh * Nc + i0) * Dc;
    float* O1 = O + ((size_t)bh * Nc + i1) * Dc;
    #pragma unroll
    for (int nf = 0; nf < 16; nf++) {
        int d = nf * 8 + 2 * lr;
        *(float2*)(O0 + d) = make_float2(o[nf].x * inv0, o[nf].y * inv0);
        *(float2*)(O1 + d) = make_float2(o[nf].z * inv1, o[nf].w * inv1);
    }
}

extern "C" void kernel_launch(void* const* d_in, const int* in_sizes, int n_in,
                              void* d_out, int out_size)
{
    const float* q = (const float*)d_in[0];
    const float* k = (const float*)d_in[1];
    const float* v = (const float*)d_in[2];
    const int* num_sink  = (const int*)d_in[3];
    const int* window_sz = (const int*)d_in[4];
    float* out = (float*)d_out;

    cudaFuncSetAttribute(pack_kernel,
                         cudaFuncAttributeMaxDynamicSharedMemorySize, PK_SMEM);
    cudaFuncSetAttribute(sink_attn_v14_kernel,
                         cudaFuncAttributeMaxDynamicSharedMemorySize, MAIN_SMEM);

    pack_kernel<<<dim3(32, 32), 256, PK_SMEM>>>(k, v);
    sink_attn_v14_kernel<<<dim3(16, 32), 256, MAIN_SMEM>>>(q, out, num_sink, window_sz);
}